// round 5
// baseline (speedup 1.0000x reference)
#include <cuda_runtime.h>
#include <cstdint>

#define CHAR_EMB 30
#define NFILT    30
#define MAXW     40
#define NCHARS   102
#define TH       128          // 4 warps, one position per warp
#define GRID     740          // 5 per SM target on 148-SM chip

typedef unsigned long long ull;

__device__ __forceinline__ ull pk2(float lo, float hi) {
    ull r;
    asm("mov.b64 %0, {%1, %2};" : "=l"(r) : "f"(lo), "f"(hi));
    return r;
}
__device__ __forceinline__ void upk2(float& lo, float& hi, ull v) {
    asm("mov.b64 {%0, %1}, %2;" : "=f"(lo), "=f"(hi) : "l"(v));
}
__device__ __forceinline__ ull fma2(ull a, ull b, ull c) {
    ull d;
    asm("fma.rn.f32x2 %0, %1, %2, %3;" : "=l"(d) : "l"(a), "l"(b), "l"(c));
    return d;
}
__device__ __forceinline__ ull mul2(ull a, ull b) {
    ull d;
    asm("mul.rn.f32x2 %0, %1, %2;" : "=l"(d) : "l"(a), "l"(b));
    return d;
}

// Warp-autonomous encoder. Each warp owns one position at a time:
//   lane e gathers x[e, 0..39] via shfl-broadcast ids + one smem emb row read,
//   packs both conv phases into registers, then runs 30 filters with weights
//   streamed from a pre-packed smem table. No __syncthreads after table init.
__global__ __launch_bounds__(TH, 4)
void encoder_kernel(const int*    __restrict__ char_ids,
                    const int*    __restrict__ word_ids,
                    const float*  __restrict__ char_emb,
                    const float*  __restrict__ conv_w,
                    const float*  __restrict__ conv_b,
                    const float4* __restrict__ glove4,
                    float*        __restrict__ out,
                    int n_pos)
{
    __shared__ float emb_s[NCHARS * 32];       // [char][e], padded row 32
    __shared__ ull   ws[900 * 4];              // per filter: w0pair,w1pair,w2pair,biaspair

    const int tid  = threadIdx.x;
    const int lane = tid & 31;
    const int wrp  = tid >> 5;

    for (int i = tid; i < NCHARS * CHAR_EMB; i += TH)
        emb_s[(i / CHAR_EMB) * 32 + (i % CHAR_EMB)] = char_emb[i];
    for (int f = tid; f < 900; f += TH) {
        const float* wp = conv_w + (size_t)f * 3;
        ws[f * 4 + 0] = pk2(wp[0], wp[0]);
        ws[f * 4 + 1] = pk2(wp[1], wp[1]);
        ws[f * 4 + 2] = pk2(wp[2], wp[2]);
        ws[f * 4 + 3] = pk2(conv_b[f], conv_b[f]);
    }
    __syncthreads();

    const int wstride = gridDim.x * (TH / 32);
    int p = blockIdx.x * (TH / 32) + wrp;
    if (p >= n_pos) return;

    // ids for current position: lane l<20 holds chars (2l, 2l+1)
    int2 c = make_int2(0, 0);
    if (lane < 20) c = reinterpret_cast<const int2*>(char_ids)[(size_t)p * 20 + lane];

    while (true) {
        const int pn = p + wstride;
        int2 cn = make_int2(0, 0);
        if (pn < n_pos && lane < 20)
            cn = reinterpret_cast<const int2*>(char_ids)[(size_t)pn * 20 + lane];

        // ---- gather + pack x[e = lane, t] into registers ----
        ull xe[20], xo[19];
        {
#define EV(t) emb_s[__shfl_sync(0xFFFFFFFFu, ((t) & 1) ? c.y : c.x, (t) >> 1) * 32 + lane]
            float x0 = EV(0);
            float x1 = EV(1);
            xe[0] = pk2(x0, x1);
#pragma unroll
            for (int i = 1; i < 20; i++) {
                float x2 = EV(2 * i);
                float x3 = EV(2 * i + 1);
                xe[i]     = pk2(x2, x3);
                xo[i - 1] = pk2(x1, x2);
                x1 = x3;
            }
#undef EV
        }

        // ---- 30 filters, weights from packed smem table ----
        if (lane < CHAR_EMB) {
            const ulonglong2* wp2 =
                reinterpret_cast<const ulonglong2*>(ws) + lane * NFILT * 2;
            float* outp = out + (size_t)p * 1000 + lane * NFILT;
#pragma unroll 2
            for (int f = 0; f < NFILT; f++) {
                const ulonglong2 wa = wp2[f * 2];       // w0pair, w1pair
                const ulonglong2 wb = wp2[f * 2 + 1];   // w2pair, biaspair
                float m0 = -3.402823466e+38f, m1 = -3.402823466e+38f;
#pragma unroll
                for (int i = 0; i < 19; i++) {
                    ull acc = mul2(wb.x, xe[i + 1]);
                    acc = fma2(wa.y, xo[i], acc);
                    acc = fma2(wa.x, xe[i], acc);
                    float lo, hi;
                    upk2(lo, hi, acc);
                    m0 = fmaxf(m0, lo);
                    m1 = fmaxf(m1, hi);
                }
                float bl, bh;
                upk2(bl, bh, wb.y);
                outp[f] = fmaxf(m0, m1) + bl;
            }
        }

        // ---- glove gather: 25 float4 per position ----
        if (lane < 25) {
            const int wid = word_ids[p];
            reinterpret_cast<float4*>(out)[(size_t)p * 250 + 225 + lane] =
                glove4[(size_t)wid * 25 + lane];
        }

        if (pn >= n_pos) break;
        p = pn;
        c = cn;
    }
}

extern "C" void kernel_launch(void* const* d_in, const int* in_sizes, int n_in,
                              void* d_out, int out_size)
{
    const int*   char_ids = (const int*)d_in[0];
    const int*   word_ids = (const int*)d_in[1];
    const float* char_emb = (const float*)d_in[2];
    const float* conv_w   = (const float*)d_in[3];
    const float* conv_b   = (const float*)d_in[4];
    const float* glove    = (const float*)d_in[5];
    float*       out      = (float*)d_out;

    const int n_pos = in_sizes[1];   // B*S

    int blocks = GRID;
    if (blocks * (TH / 32) > n_pos) blocks = (n_pos + TH / 32 - 1) / (TH / 32);
    encoder_kernel<<<blocks, TH>>>(char_ids, word_ids, char_emb, conv_w, conv_b,
                                   (const float4*)glove, out, n_pos);
}